// round 13
// baseline (speedup 1.0000x reference)
#include <cuda_runtime.h>
#include <cstdint>

#define BATCH 64
#define SEQ   1024
#define DIN   256
#define UNITS 512
#define NR4   (SEQ / 4)     // 256 four-step rounds

// ============================ Scan configuration ============================
#define TB 8
#define TU 32
#define NBC (BATCH / TB)    // 8 batch groups
#define NUC (UNITS / TU)    // 16 CTAs per group
#define SCAN_THREADS 512
#define NW 16
#define KCH (UNITS / NW)    // 32 k per warp
#define HS_STRIDE 12
#define RED_STRIDE 9

// Ping-pong tagged hidden state: word = (tag << 32) | float_bits(h)
__device__ unsigned long long g_Hx[2][BATCH * UNITS];
// Transition matrix powers
__device__ float g_A [UNITS * UNITS];   // A  = diag(1-it) + U*diag(it)
__device__ float g_A2[UNITS * UNITS];
__device__ float g_A3[UNITS * UNITS];
__device__ float g_A4[UNITS * UNITS];
// Per-round input combinations
__device__ float g_Gm2[BATCH * NR4 * UNITS];   // g0 A + g1
__device__ float g_Gm3[BATCH * NR4 * UNITS];   // Gm2 A + g2
__device__ float g_Psi[BATCH * NR4 * UNITS];   // Gm3 A + g3

// packed fp32x2 FMA (2x fp32 rate on sm_103a; ptxas never auto-emits this)
#define FMA2(acc, h, u) asm("fma.rn.f32x2 %0, %1, %2, %0;" : "+l"(acc) : "l"(h), "l"(u))

__device__ __forceinline__ unsigned long long dup_f32(float v) {
    unsigned long long r;
    asm("mov.b64 %0, {%1, %1};" : "=l"(r) : "f"(v));
    return r;
}
__device__ __forceinline__ void unpack2(unsigned long long v, float& lo, float& hi) {
    asm("mov.b64 {%0, %1}, %2;" : "=f"(lo), "=f"(hi) : "l"(v));
}
__device__ __forceinline__ unsigned long long ld_poll(const unsigned long long* p) {
    unsigned long long v;
    asm volatile("ld.relaxed.gpu.global.b64 %0, [%1];" : "=l"(v) : "l"(p));
    return v;
}
__device__ __forceinline__ void st_tagged(unsigned long long* p, float h, unsigned tag) {
    unsigned long long v = ((unsigned long long)tag << 32) | (unsigned long long)__float_as_uint(h);
    asm volatile("st.relaxed.gpu.global.b64 [%0], %1;" :: "l"(p), "l"(v));
}

// ====================== clear tag buffers (cross-replay) ====================
__global__ void ltc_clear()
{
    unsigned long long* p = &g_Hx[0][0];
    int i = blockIdx.x * blockDim.x + threadIdx.x;
    const int total = 2 * BATCH * UNITS;
    for (; i < total; i += gridDim.x * blockDim.x)
        p[i] = 0ull;
}

// ====================== build A = diag(1-it) + U*diag(it) ===================
__global__ void build_A(const float* __restrict__ U, const float* __restrict__ tau)
{
    int u = threadIdx.x;
    int k = blockIdx.x;
    float it = 1.0f / tau[u];
    float v = U[k * UNITS + u] * it;
    if (k == u) v += 1.0f - it;
    g_A[k * UNITS + u] = v;
}

// ============ small 512^3 GEMM (64-tile) for matrix powers ==================
#define GBM 64
#define GBN 64
#define GBK 16

__device__ __forceinline__ void sq_body(const float* __restrict__ Am,
                                        const float* __restrict__ Bm,
                                        float* __restrict__ Cm,
                                        int bx, int by, int tid)
{
    __shared__ float As[GBK][GBM + 4];
    __shared__ float Bs[GBK][GBN];

    const int arow = tid >> 2, akq = tid & 3;
    const int bkr  = tid >> 4, bnq = tid & 15;
    const int ty   = tid >> 4, tx  = tid & 15;

    unsigned long long acc[4][2];
    #pragma unroll
    for (int i = 0; i < 4; i++) { acc[i][0] = 0ull; acc[i][1] = 0ull; }

    const size_t arow_g = (size_t)(by * GBM + arow) * UNITS;

    for (int k0 = 0; k0 < UNITS; k0 += GBK) {
        float4 av = *reinterpret_cast<const float4*>(&Am[arow_g + k0 + akq * 4]);
        As[akq * 4 + 0][arow] = av.x;
        As[akq * 4 + 1][arow] = av.y;
        As[akq * 4 + 2][arow] = av.z;
        As[akq * 4 + 3][arow] = av.w;
        float4 bv = *reinterpret_cast<const float4*>(&Bm[(size_t)(k0 + bkr) * UNITS + bx * GBN + bnq * 4]);
        *reinterpret_cast<float4*>(&Bs[bkr][bnq * 4]) = bv;
        __syncthreads();
        #pragma unroll
        for (int k = 0; k < GBK; k++) {
            float4 am = *reinterpret_cast<const float4*>(&As[k][ty * 4]);
            ulonglong2 bn = *reinterpret_cast<const ulonglong2*>(&Bs[k][tx * 4]);
            unsigned long long a0 = dup_f32(am.x), a1 = dup_f32(am.y);
            unsigned long long a2 = dup_f32(am.z), a3 = dup_f32(am.w);
            FMA2(acc[0][0], bn.x, a0); FMA2(acc[0][1], bn.y, a0);
            FMA2(acc[1][0], bn.x, a1); FMA2(acc[1][1], bn.y, a1);
            FMA2(acc[2][0], bn.x, a2); FMA2(acc[2][1], bn.y, a2);
            FMA2(acc[3][0], bn.x, a3); FMA2(acc[3][1], bn.y, a3);
        }
        __syncthreads();
    }
    const int n0 = bx * GBN + tx * 4;
    #pragma unroll
    for (int i = 0; i < 4; i++) {
        int m = by * GBM + ty * 4 + i;
        float c0, c1, c2, c3;
        unpack2(acc[i][0], c0, c1);
        unpack2(acc[i][1], c2, c3);
        *reinterpret_cast<float4*>(&Cm[(size_t)m * UNITS + n0]) = make_float4(c0, c1, c2, c3);
    }
}

__global__ void __launch_bounds__(256)
gemm_sq(const float* __restrict__ Am, const float* __restrict__ Bm, float* __restrict__ Cm)
{
    sq_body(Am, Bm, Cm, blockIdx.x, blockIdx.y, threadIdx.x);
}

// z=0: A3 = A2 @ A;  z=1: A4 = A2 @ A2  (one launch, independent)
__global__ void __launch_bounds__(256)
gemm_sq_dual()
{
    if (blockIdx.z == 0) sq_body(g_A2, g_A,  g_A3, blockIdx.x, blockIdx.y, threadIdx.x);
    else                 sq_body(g_A2, g_A2, g_A4, blockIdx.x, blockIdx.y, threadIdx.x);
}

// ==================== High-efficiency 128x128 GEMM core =====================
// 256 threads, 8x8 micro-tile, A stored DUPLICATED in smem (no in-loop MOVs),
// ping-pong buffers, one __syncthreads per 16-wide k-block.
#define TBM 128
#define TBN 128
#define TBK 16
#define ADUP_BUF (TBK * 2 * TBM)   // 4096 floats per buffer
#define BS_BUF   (TBK * TBN)       // 2048 floats per buffer
#define CORE_SMEM ((2 * ADUP_BUF + 2 * BS_BUF) * 4)  // 49152 B

__device__ __forceinline__ void store_adup(float* Ad, int buf, int lkq, int lrow,
                                           float4 a0, float4 a1)
{
    unsigned long long* d = reinterpret_cast<unsigned long long*>(Ad + buf * ADUP_BUF);
    d[(lkq + 0) * TBM + lrow] = dup_f32(a0.x);
    d[(lkq + 1) * TBM + lrow] = dup_f32(a0.y);
    d[(lkq + 2) * TBM + lrow] = dup_f32(a0.z);
    d[(lkq + 3) * TBM + lrow] = dup_f32(a0.w);
    d[(lkq + 4) * TBM + lrow] = dup_f32(a1.x);
    d[(lkq + 5) * TBM + lrow] = dup_f32(a1.y);
    d[(lkq + 6) * TBM + lrow] = dup_f32(a1.z);
    d[(lkq + 7) * TBM + lrow] = dup_f32(a1.w);
}
__device__ __forceinline__ void store_b(float* Bsm, int buf, int brow, int bnq,
                                        float4 b0, float4 b1)
{
    float* d = Bsm + buf * BS_BUF + brow * TBN + bnq;
    *reinterpret_cast<float4*>(d)     = b0;
    *reinterpret_cast<float4*>(d + 4) = b1;
}
__device__ __forceinline__ float4 acc_f4(unsigned long long a, unsigned long long b)
{
    float x0, x1, x2, x3;
    unpack2(a, x0, x1);
    unpack2(b, x2, x3);
    return make_float4(x0, x1, x2, x3);
}

// Core mainloop macro: computes acc[8][4] over K using APTR (A row base per
// thread), AVALID predicate, BPTR (B column base: Bmat + n0 + lane cols).
#define CORE_MAIN(K_TOTAL, APTR, AVALID, BPTR)                                            \
    unsigned long long acc[8][4];                                                          \
    _Pragma("unroll")                                                                      \
    for (int i = 0; i < 8; i++) { acc[i][0]=0; acc[i][1]=0; acc[i][2]=0; acc[i][3]=0; }   \
    const int lrow = tid >> 1, lkq = (tid & 1) * 8;                                        \
    const int brow = tid >> 4, bnq = (tid & 15) * 8;                                       \
    float4 pa0, pa1, pb0, pb1;                                                             \
    pa0 = make_float4(0.f,0.f,0.f,0.f); pa1 = pa0;                                         \
    if (AVALID) {                                                                          \
        pa0 = *reinterpret_cast<const float4*>((APTR) + lkq);                              \
        pa1 = *reinterpret_cast<const float4*>((APTR) + lkq + 4);                          \
    }                                                                                      \
    pb0 = *reinterpret_cast<const float4*>((BPTR) + (size_t)brow * UNITS);                 \
    pb1 = *reinterpret_cast<const float4*>((BPTR) + (size_t)brow * UNITS + 4);             \
    store_adup(Ad, 0, lkq, lrow, pa0, pa1);                                                \
    store_b(Bsm, 0, brow, bnq, pb0, pb1);                                                  \
    __syncthreads();                                                                       \
    const int NKB = (K_TOTAL) / TBK;                                                       \
    for (int kb = 0; kb < NKB; kb++) {                                                     \
        const int cur = kb & 1;                                                            \
        if (kb + 1 < NKB) {                                                                \
            const int ko = (kb + 1) * TBK;                                                 \
            if (AVALID) {                                                                  \
                pa0 = *reinterpret_cast<const float4*>((APTR) + ko + lkq);                 \
                pa1 = *reinterpret_cast<const float4*>((APTR) + ko + lkq + 4);             \
            }                                                                              \
            pb0 = *reinterpret_cast<const float4*>((BPTR) + (size_t)(ko + brow) * UNITS);  \
            pb1 = *reinterpret_cast<const float4*>((BPTR) + (size_t)(ko + brow) * UNITS + 4);\
        }                                                                                  \
        const float* adb = Ad + cur * ADUP_BUF + ty * 16;                                  \
        const float* bsb = Bsm + cur * BS_BUF + tx * 8;                                    \
        _Pragma("unroll")                                                                  \
        for (int k = 0; k < TBK; k++) {                                                    \
            const ulonglong2* aq = reinterpret_cast<const ulonglong2*>(adb + k * (2*TBM)); \
            ulonglong2 q0 = aq[0], q1 = aq[1], q2 = aq[2], q3 = aq[3];                     \
            const ulonglong2* bq = reinterpret_cast<const ulonglong2*>(bsb + k * TBN);     \
            ulonglong2 p0 = bq[0], p1 = bq[1];                                             \
            FMA2(acc[0][0], p0.x, q0.x); FMA2(acc[0][1], p0.y, q0.x);                      \
            FMA2(acc[0][2], p1.x, q0.x); FMA2(acc[0][3], p1.y, q0.x);                      \
            FMA2(acc[1][0], p0.x, q0.y); FMA2(acc[1][1], p0.y, q0.y);                      \
            FMA2(acc[1][2], p1.x, q0.y); FMA2(acc[1][3], p1.y, q0.y);                      \
            FMA2(acc[2][0], p0.x, q1.x); FMA2(acc[2][1], p0.y, q1.x);                      \
            FMA2(acc[2][2], p1.x, q1.x); FMA2(acc[2][3], p1.y, q1.x);                      \
            FMA2(acc[3][0], p0.x, q1.y); FMA2(acc[3][1], p0.y, q1.y);                      \
            FMA2(acc[3][2], p1.x, q1.y); FMA2(acc[3][3], p1.y, q1.y);                      \
            FMA2(acc[4][0], p0.x, q2.x); FMA2(acc[4][1], p0.y, q2.x);                      \
            FMA2(acc[4][2], p1.x, q2.x); FMA2(acc[4][3], p1.y, q2.x);                      \
            FMA2(acc[5][0], p0.x, q2.y); FMA2(acc[5][1], p0.y, q2.y);                      \
            FMA2(acc[5][2], p1.x, q2.y); FMA2(acc[5][3], p1.y, q2.y);                      \
            FMA2(acc[6][0], p0.x, q3.x); FMA2(acc[6][1], p0.y, q3.x);                      \
            FMA2(acc[6][2], p1.x, q3.x); FMA2(acc[6][3], p1.y, q3.x);                      \
            FMA2(acc[7][0], p0.x, q3.y); FMA2(acc[7][1], p0.y, q3.y);                      \
            FMA2(acc[7][2], p1.x, q3.y); FMA2(acc[7][3], p1.y, q3.y);                      \
        }                                                                                  \
        if (kb + 1 < NKB) {                                                                \
            store_adup(Ad, cur ^ 1, lkq, lrow, pa0, pa1);                                  \
            store_b(Bsm, cur ^ 1, brow, bnq, pb0, pb1);                                    \
        }                                                                                  \
        __syncthreads();                                                                   \
    }

// ============ Phase 1: G = inv_tau * (x@W + b), 128x128 tiles ===============
__global__ void __launch_bounds__(256, 2)
ltc_gemm_t(const float* __restrict__ X,
           const float* __restrict__ Wm,
           const float* __restrict__ bias,
           const float* __restrict__ tau,
           float* __restrict__ G)
{
    extern __shared__ float sm[];
    float* Ad  = sm;
    float* Bsm = sm + 2 * ADUP_BUF;

    const int tid = threadIdx.x;
    const int bx = blockIdx.x, by = blockIdx.y;
    const int ty = tid >> 4, tx = tid & 15;
    const int n0 = bx * TBN;

    const float* aptr_base = X + (size_t)(by * TBM + (tid >> 1)) * DIN;
    const float* bptr_base = Wm + n0 + ((tid & 15) * 8);

    CORE_MAIN(DIN, aptr_base, true, bptr_base)

    // Epilogue: G = it * (acc + b)
    const int nc = n0 + tx * 8;
    float4 t0 = *reinterpret_cast<const float4*>(&tau[nc]);
    float4 t1 = *reinterpret_cast<const float4*>(&tau[nc + 4]);
    float4 bb0 = *reinterpret_cast<const float4*>(&bias[nc]);
    float4 bb1 = *reinterpret_cast<const float4*>(&bias[nc + 4]);
    float4 i0 = make_float4(1.f/t0.x, 1.f/t0.y, 1.f/t0.z, 1.f/t0.w);
    float4 i1 = make_float4(1.f/t1.x, 1.f/t1.y, 1.f/t1.z, 1.f/t1.w);

    #pragma unroll
    for (int i = 0; i < 8; i++) {
        size_t m = (size_t)(by * TBM + ty * 8 + i);
        float4 v0 = acc_f4(acc[i][0], acc[i][1]);
        float4 v1 = acc_f4(acc[i][2], acc[i][3]);
        v0.x = i0.x * (v0.x + bb0.x); v0.y = i0.y * (v0.y + bb0.y);
        v0.z = i0.z * (v0.z + bb0.z); v0.w = i0.w * (v0.w + bb0.w);
        v1.x = i1.x * (v1.x + bb1.x); v1.y = i1.y * (v1.y + bb1.y);
        v1.z = i1.z * (v1.z + bb1.z); v1.w = i1.w * (v1.w + bb1.w);
        *reinterpret_cast<float4*>(&G[m * UNITS + nc])     = v0;
        *reinterpret_cast<float4*>(&G[m * UNITS + nc + 4]) = v1;
    }
}

// ===== Gamma chain: dst[b,r] = Aop_row(b,r) @ g_A + G[b][4r+addc] ===========
__global__ void __launch_bounds__(256, 2)
gam_chain_t(const float* __restrict__ Aop, size_t sB, size_t sR,
            const float* __restrict__ G, int addc, float* __restrict__ dst)
{
    extern __shared__ float sm[];
    float* Ad  = sm;
    float* Bsm = sm + 2 * ADUP_BUF;

    const int tid = threadIdx.x;
    const int bx = blockIdx.x, by = blockIdx.y;
    const int ty = tid >> 4, tx = tid & 15;
    const int n0 = bx * TBN;

    const int bglob = by >> 1;
    const int r0    = (by & 1) * TBM;

    const float* aptr_base = Aop + (size_t)bglob * sB + (size_t)(r0 + (tid >> 1)) * sR;
    const float* bptr_base = g_A + n0 + ((tid & 15) * 8);

    CORE_MAIN(UNITS, aptr_base, true, bptr_base)

    const int nc = n0 + tx * 8;
    #pragma unroll
    for (int i = 0; i < 8; i++) {
        int r = r0 + ty * 8 + i;
        float4 v0 = acc_f4(acc[i][0], acc[i][1]);
        float4 v1 = acc_f4(acc[i][2], acc[i][3]);
        size_t go = ((size_t)bglob * SEQ + 4 * r + addc) * UNITS + nc;
        float4 g0 = *reinterpret_cast<const float4*>(&G[go]);
        float4 g1 = *reinterpret_cast<const float4*>(&G[go + 4]);
        v0.x += g0.x; v0.y += g0.y; v0.z += g0.z; v0.w += g0.w;
        v1.x += g1.x; v1.y += g1.y; v1.z += g1.z; v1.w += g1.w;
        size_t dof = ((size_t)bglob * NR4 + r) * UNITS + nc;
        *reinterpret_cast<float4*>(&dst[dof])     = v0;
        *reinterpret_cast<float4*>(&dst[dof + 4]) = v1;
    }
}

// ===== Post: out[4r+c] = h_{4r} @ A^{c+1} + {g_{4r}, Gm2, Gm3} ==============
// A-operand rows = out[4r-1] (scan output), zeros for r = 0. grid (12, 128).
__global__ void __launch_bounds__(256, 2)
ltc_post_t(float* __restrict__ out)
{
    extern __shared__ float sm[];
    float* Ad  = sm;
    float* Bsm = sm + 2 * ADUP_BUF;

    const int tid = threadIdx.x;
    const int bx = blockIdx.x, by = blockIdx.y;
    const int ty = tid >> 4, tx = tid & 15;
    const int c  = bx >> 2;                 // 0 -> A, 1 -> A2, 2 -> A3
    const int n0 = (bx & 3) * TBN;

    const int bglob = by >> 1;
    const int r0    = (by & 1) * TBM;

    const float* Bsrc = (c == 0) ? g_A : (c == 1) ? g_A2 : g_A3;

    const int rr_l = r0 + (tid >> 1);
    const bool avalid = (rr_l > 0);
    const float* aptr_base = out + ((size_t)bglob * SEQ + 4 * rr_l - 1) * UNITS;
    const float* bptr_base = Bsrc + n0 + ((tid & 15) * 8);

    CORE_MAIN(UNITS, aptr_base, avalid, bptr_base)

    const int nc = n0 + tx * 8;
    #pragma unroll
    for (int i = 0; i < 8; i++) {
        int r = r0 + ty * 8 + i;
        float4 v0 = acc_f4(acc[i][0], acc[i][1]);
        float4 v1 = acc_f4(acc[i][2], acc[i][3]);
        size_t doff = ((size_t)bglob * SEQ + 4 * r + c) * UNITS + nc;
        float4 a0, a1;
        if (c == 0) {
            a0 = *reinterpret_cast<const float4*>(&out[doff]);
            a1 = *reinterpret_cast<const float4*>(&out[doff + 4]);
        } else {
            const float* src = (c == 1) ? g_Gm2 : g_Gm3;
            size_t so = ((size_t)bglob * NR4 + r) * UNITS + nc;
            a0 = *reinterpret_cast<const float4*>(&src[so]);
            a1 = *reinterpret_cast<const float4*>(&src[so + 4]);
        }
        v0.x += a0.x; v0.y += a0.y; v0.z += a0.z; v0.w += a0.w;
        v1.x += a1.x; v1.y += a1.y; v1.z += a1.z; v1.w += a1.w;
        *reinterpret_cast<float4*>(&out[doff])     = v0;
        *reinterpret_cast<float4*>(&out[doff + 4]) = v1;
    }
}

// ============================ Phase 2: LTC scan =============================
// Per round r (4 timesteps): h_{4r+4} = h_{4r} @ A4 + Psi_r -> out[4r+3].
__global__ void __launch_bounds__(SCAN_THREADS, 1)
ltc_scan(float* __restrict__ out)
{
    const int ju   = blockIdx.x;
    const int ib   = blockIdx.y;
    const int tid  = threadIdx.x;
    const int lane = tid & 31;
    const int w    = tid >> 5;
    const int u    = ju * TU + lane;
    const int kb   = w * KCH;
    const int bg0  = ib * TB;

    __shared__ float Hs[UNITS * HS_STRIDE];
    __shared__ float Red[NW * 32 * RED_STRIDE];

    unsigned long long UU[KCH];
    #pragma unroll
    for (int i = 0; i < KCH; i++)
        UU[i] = dup_f32(g_A4[(size_t)(kb + i) * UNITS + u]);

    if (tid < 256)
        st_tagged(&g_Hx[0][(bg0 + w) * UNITS + u], 0.0f, 1u);

    int cur = 0;
    for (int r = 0; r < NR4; r++) {
        const unsigned want = (unsigned)(r + 1);

        float psi = 0.0f;
        size_t o3 = 0;
        if (tid < 256) {
            o3  = ((size_t)(bg0 + w) * SEQ + 4 * r + 3) * UNITS + u;
            psi = g_Psi[((size_t)(bg0 + w) * NR4 + r) * UNITS + u];
        }

        unsigned long long v[8];
        {
            const unsigned long long* src = &g_Hx[cur][tid];
            bool ok;
            do {
                ok = true;
                #pragma unroll
                for (int b = 0; b < 8; b++)
                    v[b] = ld_poll(&src[(size_t)(bg0 + b) * UNITS]);
                #pragma unroll
                for (int b = 0; b < 8; b++)
                    ok &= ((unsigned)(v[b] >> 32) == want);
            } while (!ok);
        }
        {
            float4* dst = reinterpret_cast<float4*>(&Hs[tid * HS_STRIDE]);
            dst[0] = make_float4(__uint_as_float((unsigned)v[0]), __uint_as_float((unsigned)v[1]),
                                 __uint_as_float((unsigned)v[2]), __uint_as_float((unsigned)v[3]));
            dst[1] = make_float4(__uint_as_float((unsigned)v[4]), __uint_as_float((unsigned)v[5]),
                                 __uint_as_float((unsigned)v[6]), __uint_as_float((unsigned)v[7]));
        }
        __syncthreads();

        unsigned long long c0 = 0, c1 = 0, c2 = 0, c3 = 0;
        #pragma unroll
        for (int i = 0; i < KCH; i++) {
            const ulonglong2* hv = reinterpret_cast<const ulonglong2*>(&Hs[(kb + i) * HS_STRIDE]);
            ulonglong2 hA = hv[0];
            ulonglong2 hB = hv[1];
            FMA2(c0, hA.x, UU[i]);
            FMA2(c1, hA.y, UU[i]);
            FMA2(c2, hB.x, UU[i]);
            FMA2(c3, hB.y, UU[i]);
        }
        {
            float* rr = &Red[(w * 32 + lane) * RED_STRIDE];
            float x0, x1;
            unpack2(c0, x0, x1); rr[0] = x0; rr[1] = x1;
            unpack2(c1, x0, x1); rr[2] = x0; rr[3] = x1;
            unpack2(c2, x0, x1); rr[4] = x0; rr[5] = x1;
            unpack2(c3, x0, x1); rr[6] = x0; rr[7] = x1;
        }
        __syncthreads();

        if (tid < 256) {
            float s = 0.0f;
            #pragma unroll
            for (int ww = 0; ww < NW; ww++)
                s += Red[(ww * 32 + lane) * RED_STRIDE + w];
            float hn = s + psi;
            out[o3] = hn;
            st_tagged(&g_Hx[cur ^ 1][(bg0 + w) * UNITS + u], hn, (unsigned)(r + 2));
        }
        cur ^= 1;
    }
}

// ================================ Launcher ==================================
extern "C" void kernel_launch(void* const* d_in, const int* in_sizes, int n_in,
                              void* d_out, int out_size)
{
    const float* x   = (const float*)d_in[0];   // [64,1024,256]
    const float* Wm  = (const float*)d_in[1];   // [256,512]
    const float* Um  = (const float*)d_in[2];   // [512,512]
    const float* bb  = (const float*)d_in[3];   // [512]
    const float* tau = (const float*)d_in[4];   // [512]
    float* out = (float*)d_out;                 // [64,1024,512]

    (void)in_sizes; (void)n_in; (void)out_size;

    ltc_clear<<<128, 256>>>();

    build_A<<<UNITS, UNITS>>>(Um, tau);
    float *pA, *pA2, *pGm2, *pGm3, *pPsi;
    cudaGetSymbolAddress((void**)&pA,   g_A);
    cudaGetSymbolAddress((void**)&pA2,  g_A2);
    cudaGetSymbolAddress((void**)&pGm2, g_Gm2);
    cudaGetSymbolAddress((void**)&pGm3, g_Gm3);
    cudaGetSymbolAddress((void**)&pPsi, g_Psi);

    gemm_sq<<<dim3(UNITS / GBN, UNITS / GBM), 256>>>(pA, pA, pA2);
    gemm_sq_dual<<<dim3(UNITS / GBN, UNITS / GBM, 2), 256>>>();

    cudaFuncSetAttribute(ltc_gemm_t, cudaFuncAttributeMaxDynamicSharedMemorySize, CORE_SMEM);
    cudaFuncSetAttribute(gam_chain_t, cudaFuncAttributeMaxDynamicSharedMemorySize, CORE_SMEM);
    cudaFuncSetAttribute(ltc_post_t, cudaFuncAttributeMaxDynamicSharedMemorySize, CORE_SMEM);

    // G = inv_tau * (x@W + b) -> out
    ltc_gemm_t<<<dim3(UNITS / TBN, (BATCH * SEQ) / TBM), 256, CORE_SMEM>>>(x, Wm, bb, tau, out);

    // Gamma chain: Gm2 = g0 A + g1; Gm3 = Gm2 A + g2; Psi = Gm3 A + g3
    dim3 gg(UNITS / TBN, (BATCH * NR4) / TBM);   // (4, 128)
    gam_chain_t<<<gg, 256, CORE_SMEM>>>(out,  (size_t)SEQ * UNITS, (size_t)4 * UNITS, out, 1, pGm2);
    gam_chain_t<<<gg, 256, CORE_SMEM>>>(pGm2, (size_t)NR4 * UNITS, (size_t)UNITS,     out, 2, pGm3);
    gam_chain_t<<<gg, 256, CORE_SMEM>>>(pGm3, (size_t)NR4 * UNITS, (size_t)UNITS,     out, 3, pPsi);

    // Four-step scan -> out[4r+3]
    ltc_scan<<<dim3(NUC, NBC), SCAN_THREADS>>>(out);

    // Post: out[4r+c] = h_{4r} A^{c+1} + {g, Gm2, Gm3}, c = 0,1,2
    ltc_post_t<<<dim3(12, (BATCH * NR4) / TBM), 256, CORE_SMEM>>>(out);
}